// round 2
// baseline (speedup 1.0000x reference)
#include <cuda_runtime.h>

#define NB 2
#define MID 64
#define BAND 8
#define HS 96
#define HQ 384
#define HQP 385
#define LTOT 576
#define PP 25
#define QW 96
#define QPOS (QW*QW)

// ---------------- scratch (device globals; no runtime allocation) ------------
__device__ float g_kfea[NB*MID*HS*HS];        // 4.7 MB
__device__ float g_qfea[NB*MID*HQP*HQP];      // 75.9 MB, padded (row/col 384 = 0)
__device__ float g_vfea[NB*BAND*HS*HS];
__device__ float g_K[NB*MID*PP*LTOT];         // [n][c][p][l]  (unnormalized patches)
__device__ float g_ssq[NB*LTOT];
__device__ float g_scale[NB];                 // 10 / max patch norm
__device__ float g_attn[NB*QPOS*LTOT];        // scores, then softmaxed in place
__device__ float g_vT[NB*BAND*PP*LTOT];       // [n][b][p][l]
__device__ float g_res[NB*BAND*HQP*HQP];      // conv_transpose output / 6

__device__ __forceinline__ float lrelu(float v) { return v > 0.f ? v : 0.01f * v; }

// ---------------- 3x3 conv, 1 input channel -> C output channels -------------
// HOUT == HIN (normal) or HIN+1 (write directly into zero-padded layout).
template<int C, int HIN, int HOUT>
__global__ void conv_1toC(const float* __restrict__ in, const float* __restrict__ w,
                          const float* __restrict__ bias, float* __restrict__ out) {
    __shared__ float sw[C*9];
    __shared__ float sb[C];
    int t = threadIdx.x;
    for (int e = t; e < C*9; e += blockDim.x) sw[e] = w[e];
    for (int e = t; e < C;   e += blockDim.x) sb[e] = bias[e];
    __syncthreads();
    int idx = blockIdx.x * blockDim.x + t;
    int n = blockIdx.y;
    if (idx >= HOUT*HOUT) return;
    int y = idx / HOUT, x = idx % HOUT;
    bool inside = (y < HIN) && (x < HIN);
    float v[9];
#pragma unroll
    for (int dy = 0; dy < 3; dy++)
#pragma unroll
        for (int dx = 0; dx < 3; dx++) {
            int yy = y + dy - 1, xx = x + dx - 1;
            v[dy*3+dx] = (inside && yy >= 0 && yy < HIN && xx >= 0 && xx < HIN)
                         ? in[(n*HIN + yy)*HIN + xx] : 0.f;
        }
#pragma unroll 8
    for (int c = 0; c < C; c++) {
        float s = 0.f;
        if (inside) {
            s = sb[c];
#pragma unroll
            for (int k = 0; k < 9; k++) s += v[k] * sw[c*9 + k];
            s = lrelu(s);
        }
        out[((n*C + c)*HOUT + y)*HOUT + x] = s;
    }
}

// ---------------- 3x3 conv, C -> C channels ----------------------------------
template<int C, int H>
__global__ void conv_CtoC(const float* __restrict__ in, const float* __restrict__ w,
                          const float* __restrict__ bias, float* __restrict__ out) {
    __shared__ float sw[C*C*9];
    __shared__ float sb[C];
    int t = threadIdx.x;
    for (int e = t; e < C*C*9; e += blockDim.x) sw[e] = w[e];
    for (int e = t; e < C;     e += blockDim.x) sb[e] = bias[e];
    __syncthreads();
    int idx = blockIdx.x * blockDim.x + t;
    int n = blockIdx.y;
    if (idx >= C*H*H) return;
    int co  = idx / (H*H);
    int pix = idx % (H*H);
    int y = pix / H, x = pix % H;
    float s = sb[co];
    for (int ci = 0; ci < C; ci++) {
        const float* ip = in + ((size_t)(n*C + ci))*H*H;
#pragma unroll
        for (int dy = 0; dy < 3; dy++) {
            int yy = y + dy - 1;
            if (yy < 0 || yy >= H) continue;
#pragma unroll
            for (int dx = 0; dx < 3; dx++) {
                int xx = x + dx - 1;
                if (xx < 0 || xx >= H) continue;
                s += __ldg(&ip[yy*H + xx]) * sw[(co*C + ci)*9 + dy*3 + dx];
            }
        }
    }
    out[((size_t)(n*C + co)*H + y)*H + x] = lrelu(s);
}

// ---------------- gather K patches into [n][c][p][l] --------------------------
// patch element (l,c,i,j) = padded(97x97, pad idx 96)->rolled(+2,+2) k_fea.
__global__ void gather_k() {
    int bid = blockIdx.x;                 // n*1600 + c*25 + p
    int n  = bid / (MID*PP);
    int cp = bid % (MID*PP);
    int c  = cp / PP;
    int p  = cp % PP;
    int i  = p / 5, j = p % 5;
    int l  = threadIdx.x;                 // 576 threads
    int py = l / 24, px = l % 24;
    int sy = 4*py + i - 2; if (sy < 0) sy += 97;   // [-2,94] -> [0,96]
    int sx = 4*px + j - 2; if (sx < 0) sx += 97;
    float v = 0.f;
    if (sy < HS && sx < HS)
        v = g_kfea[((n*MID + c)*HS + sy)*HS + sx];
    g_K[(size_t)bid*LTOT + l] = v;
}

__global__ void gather_v() {
    int bid = blockIdx.x;                 // n*200 + b*25 + p
    int n  = bid / (BAND*PP);
    int bp = bid % (BAND*PP);
    int b  = bp / PP;
    int p  = bp % PP;
    int i  = p / 5, j = p % 5;
    int l  = threadIdx.x;
    int py = l / 24, px = l % 24;
    int sy = 4*py + i - 2; if (sy < 0) sy += 97;
    int sx = 4*px + j - 2; if (sx < 0) sx += 97;
    float v = 0.f;
    if (sy < HS && sx < HS)
        v = g_vfea[((n*BAND + b)*HS + sy)*HS + sx];
    g_vT[(size_t)bid*LTOT + l] = v;
}

// ---------------- per-patch sum of squares ------------------------------------
__global__ void ssq_kernel() {
    int n = blockIdx.x;
    int l = threadIdx.x;                  // 576 threads
    const float* base = g_K + (size_t)n*MID*PP*LTOT + l;
    float s = 0.f;
#pragma unroll 4
    for (int e = 0; e < MID*PP; e++) {
        float v = base[(size_t)e*LTOT];
        s += v*v;
    }
    g_ssq[n*LTOT + l] = s;
}

__global__ void max_kernel() {
    __shared__ float red[LTOT];
    int n = blockIdx.x;
    int t = threadIdx.x;                  // 576 threads
    red[t] = g_ssq[n*LTOT + t];
    __syncthreads();
    if (t < 64) red[t] = fmaxf(red[t], red[t + 512]);
    __syncthreads();
    for (int s = 256; s >= 1; s >>= 1) {
        if (t < s) red[t] = fmaxf(red[t], red[t + s]);
        __syncthreads();
    }
    if (t == 0) g_scale[n] = 10.f / sqrtf(red[0]);
}

// ---------------- scores GEMM: [9216 x 1600] x [1600 x 576] -------------------
// Block: 32 queries (contiguous ox, fixed oy) x 64 keys. 256 threads, 2q x 4k each.
__global__ void scores_gemm() {
    __shared__ __align__(16) float sK[PP][64];   // per-channel K slice [p][key]
    __shared__ float sQ[5][132];                 // 5 rows x 129 cols window
    int n   = blockIdx.z;
    int lt  = blockIdx.y;                        // key tile: lt*64
    int oy  = blockIdx.x / 3;
    int oxt = blockIdx.x % 3;                    // query tile: ox0 = oxt*32
    int t   = threadIdx.x;
    int li4 = t & 15;                            // key group (4 keys)
    int qi2 = t >> 4;                            // query group (2 queries)

    float a0x=0.f,a0y=0.f,a0z=0.f,a0w=0.f;
    float a1x=0.f,a1y=0.f,a1z=0.f,a1w=0.f;

    const float* Kbase = g_K + (size_t)n*MID*PP*LTOT + lt*64;
    const float* Qbase = g_qfea + (size_t)n*MID*HQP*HQP + (4*oy)*HQP + oxt*128;

    for (int c = 0; c < MID; c++) {
        __syncthreads();
        for (int e = t; e < PP*64; e += 256) {
            int p = e >> 6, ll = e & 63;
            sK[p][ll] = Kbase[((size_t)c*PP + p)*LTOT + ll];
        }
        for (int e = t; e < 5*129; e += 256) {
            int ri = e / 129, cc = e % 129;
            sQ[ri][cc] = Qbase[((size_t)c*HQP + ri)*HQP + cc];
        }
        __syncthreads();
#pragma unroll
        for (int p = 0; p < PP; p++) {
            const int i = p / 5, j = p - i*5;
            float4 kv = *reinterpret_cast<const float4*>(&sK[p][li4*4]);
            float qa = sQ[i][qi2*8 + j];
            float qb = sQ[i][qi2*8 + 4 + j];
            a0x += qa*kv.x; a0y += qa*kv.y; a0z += qa*kv.z; a0w += qa*kv.w;
            a1x += qb*kv.x; a1y += qb*kv.y; a1z += qb*kv.z; a1w += qb*kv.w;
        }
    }
    int ox = oxt*32 + qi2*2;
    size_t base = ((size_t)n*QPOS + oy*QW + ox)*LTOT + lt*64 + li4*4;
    *reinterpret_cast<float4*>(&g_attn[base])        = make_float4(a0x,a0y,a0z,a0w);
    *reinterpret_cast<float4*>(&g_attn[base + LTOT]) = make_float4(a1x,a1y,a1z,a1w);
}

// ---------------- softmax over 576 keys, one warp per position ----------------
__global__ void softmax_kernel() {
    int w    = threadIdx.x >> 5;
    int lane = threadIdx.x & 31;
    int gw = blockIdx.x * 8 + w;                 // n*QPOS + pos
    int n = gw / QPOS;
    float scale = g_scale[n];
    float* row = g_attn + (size_t)gw * LTOT;
    float v[18];
    float m = -1e30f;
#pragma unroll
    for (int k = 0; k < 18; k++) {
        v[k] = row[lane + 32*k] * scale;
        m = fmaxf(m, v[k]);
    }
#pragma unroll
    for (int o = 16; o; o >>= 1) m = fmaxf(m, __shfl_xor_sync(0xffffffffu, m, o));
    float s = 0.f;
#pragma unroll
    for (int k = 0; k < 18; k++) { v[k] = __expf(v[k] - m); s += v[k]; }
#pragma unroll
    for (int o = 16; o; o >>= 1) s += __shfl_xor_sync(0xffffffffu, s, o);
    float inv = 1.f / s;
#pragma unroll
    for (int k = 0; k < 18; k++) row[lane + 32*k] = v[k] * inv;
}

// ---------------- conv_transpose (stride 4, kernel 5), gather form ------------
__device__ __forceinline__ float dot576(const float* a_sh, const float* b_g) {
    const float4* a4 = reinterpret_cast<const float4*>(a_sh);
    const float4* b4 = reinterpret_cast<const float4*>(b_g);
    float s = 0.f;
#pragma unroll 8
    for (int k = 0; k < 144; k++) {
        float4 x = a4[k];
        float4 y = __ldg(&b4[k]);
        s += x.x*y.x + x.y*y.y + x.z*y.z + x.w*y.w;
    }
    return s;
}

__global__ void conv_transpose_kernel() {
    __shared__ __align__(16) float sA[2][9][580];   // 580: kill 576%32==0 aliasing
    int n  = blockIdx.z;
    int y  = blockIdx.y;
    int x0 = blockIdx.x * 32;
    int t  = threadIdx.x;

    int r   = y & 3;
    int oyA = y >> 2;            // kernel row i = r
    bool vA = (oyA < QW);
    int oyB = oyA - 1;           // kernel row i = 4 (only when r == 0)
    bool vB = (r == 0) && (oyB >= 0);

    int oxlo = x0/4 - 1; if (oxlo < 0) oxlo = 0;
    int oxhi = x0/4 + 7; if (oxhi > 95) oxhi = 95;
    int nox = oxhi - oxlo + 1;

    for (int e = t; e < nox*LTOT; e += 256) {
        int o = e / LTOT, ll = e % LTOT;
        int ox = oxlo + o;
        if (vA) sA[0][o][ll] = g_attn[((size_t)n*QPOS + oyA*QW + ox)*LTOT + ll];
        if (vB) sA[1][o][ll] = g_attn[((size_t)n*QPOS + oyB*QW + ox)*LTOT + ll];
    }
    __syncthreads();

    int b = t >> 5;
    int x = x0 + (t & 31);
    if (x >= HQP) return;
    int xr  = x & 3;
    int ox1 = x >> 2;
    float acc = 0.f;
    const float* vbase = g_vT + ((size_t)n*BAND + b)*PP*LTOT;
#pragma unroll
    for (int si = 0; si < 2; si++) {
        int ii  = (si == 0) ? r : 4;
        bool sv = (si == 0) ? vA : vB;
        if (!sv) continue;
        if (ox1 < QW)
            acc += dot576(&sA[si][ox1 - oxlo][0],     vbase + (ii*5 + xr)*LTOT);
        if (xr == 0 && ox1 >= 1)
            acc += dot576(&sA[si][ox1 - 1 - oxlo][0], vbase + (ii*5 + 4)*LTOT);
    }
    g_res[(((size_t)n*BAND + b)*HQP + y)*HQP + x] = acc * (1.f/6.f);
}

// ---------------- launch ------------------------------------------------------
extern "C" void kernel_launch(void* const* d_in, const int* in_sizes, int n_in,
                              void* d_out, int out_size) {
    const float* ms   = (const float*)d_in[0];
    const float* pan  = (const float*)d_in[1];
    const float* pan2 = (const float*)d_in[2];
    const float* wq = (const float*)d_in[3];
    const float* bq = (const float*)d_in[4];
    const float* wk = (const float*)d_in[5];
    const float* bk = (const float*)d_in[6];
    const float* wv = (const float*)d_in[7];
    const float* bv = (const float*)d_in[8];
    const float* wr = (const float*)d_in[9];
    const float* br = (const float*)d_in[10];
    float* out = (float*)d_out;

    void* pv;
    cudaGetSymbolAddress(&pv, g_kfea); float* kfea = (float*)pv;
    cudaGetSymbolAddress(&pv, g_qfea); float* qfea = (float*)pv;
    cudaGetSymbolAddress(&pv, g_vfea); float* vfea = (float*)pv;
    cudaGetSymbolAddress(&pv, g_res);  float* res  = (float*)pv;

    // feature convs
    conv_1toC<MID, HS, HS>  <<<dim3((HS*HS   + 255)/256, NB), 256>>>(pan2, wk, bk, kfea);
    conv_1toC<MID, HQ, HQP> <<<dim3((HQP*HQP + 255)/256, NB), 256>>>(pan,  wq, bq, qfea);
    conv_CtoC<BAND, HS>     <<<dim3((BAND*HS*HS + 255)/256, NB), 256>>>(ms, wv, bv, vfea);

    // patch gathers + norm scale
    gather_k<<<NB*MID*PP,  LTOT>>>();
    gather_v<<<NB*BAND*PP, LTOT>>>();
    ssq_kernel<<<NB, LTOT>>>();
    max_kernel<<<NB, LTOT>>>();

    // attention
    scores_gemm<<<dim3(QW*3, 9, NB), 256>>>();
    softmax_kernel<<<NB*QPOS/8, 256>>>();
    conv_transpose_kernel<<<dim3(13, HQP, NB), 256>>>();

    // final conv
    conv_CtoC<BAND, HQP><<<dim3((BAND*HQP*HQP + 255)/256, NB), 256>>>(res, wr, br, out);
}

// round 4
// speedup vs baseline: 1.6249x; 1.6249x over previous
#include <cuda_runtime.h>
#include <cuda_bf16.h>
#include <cstdint>

#define NB 2
#define MID 64
#define BAND 8
#define HS 96
#define HQ 384
#define HQP 385
#define LTOT 576
#define PP 25
#define QW 96
#define QPOS (QW*QW)

// GEMM tiling
#define GM_M 128
#define GM_N 192
#define KHALF 1600          // hi (or lo) region length
#define KROW 3200           // stored K length (hi|lo)
#define NCHUNK 75           // 3 regions x 25 chunks of 64
#define MTOT 9216

// ---------------- scratch (device globals; no runtime allocation) ------------
__device__ float g_kfea[NB*MID*HS*HS];
__device__ float g_qfea[NB*MID*HQP*HQP];      // padded (row/col 384 = 0)
__device__ float g_vfea[NB*BAND*HS*HS];
__device__ float g_K[NB*MID*PP*LTOT];         // [n][c][p][l]
__device__ float g_ssq[NB*LTOT];
__device__ float g_scale[NB];
__device__ float g_attn[NB*QPOS*LTOT];
__device__ float g_vT[NB*BAND*PP*LTOT];
__device__ float g_res[NB*BAND*HQP*HQP];
__device__ __nv_bfloat16 g_A[(size_t)NB*KROW*MTOT];  // 118 MB, k-major: [n][k][m]
__device__ __nv_bfloat16 g_B[(size_t)NB*LTOT*KROW];  // 7.4 MB, [n][l][k]

__device__ __forceinline__ float lrelu(float v) { return v > 0.f ? v : 0.01f * v; }

__device__ __forceinline__ uint32_t smem_u32(const void* p) {
    uint32_t a;
    asm("{ .reg .u64 t; cvta.to.shared.u64 t, %1; cvt.u32.u64 %0, t; }" : "=r"(a) : "l"(p));
    return a;
}
__device__ __forceinline__ void cp16(uint32_t dst, const void* src) {
    asm volatile("cp.async.cg.shared.global [%0], [%1], 16;" :: "r"(dst), "l"(src));
}
__device__ __forceinline__ void ldsm4(uint32_t* r, uint32_t a) {
    asm volatile("ldmatrix.sync.aligned.m8n8.x4.shared.b16 {%0,%1,%2,%3}, [%4];"
                 : "=r"(r[0]), "=r"(r[1]), "=r"(r[2]), "=r"(r[3]) : "r"(a));
}
__device__ __forceinline__ void ldsm4t(uint32_t* r, uint32_t a) {
    asm volatile("ldmatrix.sync.aligned.m8n8.x4.trans.shared.b16 {%0,%1,%2,%3}, [%4];"
                 : "=r"(r[0]), "=r"(r[1]), "=r"(r[2]), "=r"(r[3]) : "r"(a));
}
__device__ __forceinline__ void mma_bf16(float* c, const uint32_t* a, uint32_t b0, uint32_t b1) {
    asm volatile("mma.sync.aligned.m16n8k16.row.col.f32.bf16.bf16.f32 "
                 "{%0,%1,%2,%3}, {%4,%5,%6,%7}, {%8,%9}, {%0,%1,%2,%3};"
                 : "+f"(c[0]), "+f"(c[1]), "+f"(c[2]), "+f"(c[3])
                 : "r"(a[0]), "r"(a[1]), "r"(a[2]), "r"(a[3]), "r"(b0), "r"(b1));
}
#define SWZB(o) ((o) ^ (((o) >> 3) & 0x70))           // 128B rows
#define SWZA(o) ((o) ^ ((((o) >> 8) & 7) << 4))       // 256B rows

// ---------------- 3x3 conv, 1 -> C channels -----------------------------------
template<int C, int HIN, int HOUT>
__global__ void conv_1toC(const float* __restrict__ in, const float* __restrict__ w,
                          const float* __restrict__ bias, float* __restrict__ out) {
    __shared__ float sw[C*9];
    __shared__ float sb[C];
    int t = threadIdx.x;
    for (int e = t; e < C*9; e += blockDim.x) sw[e] = w[e];
    for (int e = t; e < C;   e += blockDim.x) sb[e] = bias[e];
    __syncthreads();
    int idx = blockIdx.x * blockDim.x + t;
    int n = blockIdx.y;
    if (idx >= HOUT*HOUT) return;
    int y = idx / HOUT, x = idx % HOUT;
    bool inside = (y < HIN) && (x < HIN);
    float v[9];
#pragma unroll
    for (int dy = 0; dy < 3; dy++)
#pragma unroll
        for (int dx = 0; dx < 3; dx++) {
            int yy = y + dy - 1, xx = x + dx - 1;
            v[dy*3+dx] = (inside && yy >= 0 && yy < HIN && xx >= 0 && xx < HIN)
                         ? in[(n*HIN + yy)*HIN + xx] : 0.f;
        }
#pragma unroll 8
    for (int c = 0; c < C; c++) {
        float s = 0.f;
        if (inside) {
            s = sb[c];
#pragma unroll
            for (int k = 0; k < 9; k++) s += v[k] * sw[c*9 + k];
            s = lrelu(s);
        }
        out[((n*C + c)*HOUT + y)*HOUT + x] = s;
    }
}

// ---------------- 3x3 conv, C -> C channels ------------------------------------
template<int C, int H>
__global__ void conv_CtoC(const float* __restrict__ in, const float* __restrict__ w,
                          const float* __restrict__ bias, float* __restrict__ out) {
    __shared__ float sw[C*C*9];
    __shared__ float sb[C];
    int t = threadIdx.x;
    for (int e = t; e < C*C*9; e += blockDim.x) sw[e] = w[e];
    for (int e = t; e < C;     e += blockDim.x) sb[e] = bias[e];
    __syncthreads();
    int idx = blockIdx.x * blockDim.x + t;
    int n = blockIdx.y;
    if (idx >= C*H*H) return;
    int co  = idx / (H*H);
    int pix = idx % (H*H);
    int y = pix / H, x = pix % H;
    float s = sb[co];
    for (int ci = 0; ci < C; ci++) {
        const float* ip = in + ((size_t)(n*C + ci))*H*H;
#pragma unroll
        for (int dy = 0; dy < 3; dy++) {
            int yy = y + dy - 1;
            if (yy < 0 || yy >= H) continue;
#pragma unroll
            for (int dx = 0; dx < 3; dx++) {
                int xx = x + dx - 1;
                if (xx < 0 || xx >= H) continue;
                s += __ldg(&ip[yy*H + xx]) * sw[(co*C + ci)*9 + dy*3 + dx];
            }
        }
    }
    out[((size_t)(n*C + co)*H + y)*H + x] = lrelu(s);
}

// ---------------- gather K/V patches -------------------------------------------
__global__ void gather_k() {
    int bid = blockIdx.x;
    int n  = bid / (MID*PP);
    int cp = bid % (MID*PP);
    int c  = cp / PP;
    int p  = cp % PP;
    int i  = p / 5, j = p % 5;
    int l  = threadIdx.x;
    int py = l / 24, px = l % 24;
    int sy = 4*py + i - 2; if (sy < 0) sy += 97;
    int sx = 4*px + j - 2; if (sx < 0) sx += 97;
    float v = 0.f;
    if (sy < HS && sx < HS)
        v = g_kfea[((n*MID + c)*HS + sy)*HS + sx];
    g_K[(size_t)bid*LTOT + l] = v;
}

__global__ void gather_v() {
    int bid = blockIdx.x;
    int n  = bid / (BAND*PP);
    int bp = bid % (BAND*PP);
    int b  = bp / PP;
    int p  = bp % PP;
    int i  = p / 5, j = p % 5;
    int l  = threadIdx.x;
    int py = l / 24, px = l % 24;
    int sy = 4*py + i - 2; if (sy < 0) sy += 97;
    int sx = 4*px + j - 2; if (sx < 0) sx += 97;
    float v = 0.f;
    if (sy < HS && sx < HS)
        v = g_vfea[((n*BAND + b)*HS + sy)*HS + sx];
    g_vT[(size_t)bid*LTOT + l] = v;
}

// ---------------- per-patch sum of squares + max --------------------------------
__global__ void ssq_kernel() {
    int n = blockIdx.x;
    int l = threadIdx.x;
    const float* base = g_K + (size_t)n*MID*PP*LTOT + l;
    float s = 0.f;
#pragma unroll 4
    for (int e = 0; e < MID*PP; e++) {
        float v = base[(size_t)e*LTOT];
        s += v*v;
    }
    g_ssq[n*LTOT + l] = s;
}

__global__ void max_kernel() {
    __shared__ float red[LTOT];
    int n = blockIdx.x;
    int t = threadIdx.x;
    red[t] = g_ssq[n*LTOT + t];
    __syncthreads();
    if (t < 64) red[t] = fmaxf(red[t], red[t + 512]);
    __syncthreads();
    for (int s = 256; s >= 1; s >>= 1) {
        if (t < s) red[t] = fmaxf(red[t], red[t + s]);
        __syncthreads();
    }
    if (t == 0) g_scale[n] = 10.f / sqrtf(red[0]);
}

// ---------------- im2col Q -> k-major bf16 A (hi|lo) -----------------------------
// A[n][k][m]; k = c*25+p (hi), +1600 (lo); m = oy*96 + ox. Coalesced uint32 writes.
__global__ void im2col_q() {
    __shared__ float sq[4][5][388];
    int oy = blockIdx.x;
    int cg = blockIdx.y;       // 16 groups of 4 channels
    int n  = blockIdx.z;
    int t  = threadIdx.x;
    for (int e = t; e < 4*5*385; e += 256) {
        int c = e / 1925, rem = e % 1925, r = rem / 385, x = rem % 385;
        sq[c][r][x] = g_qfea[(((size_t)(n*MID + cg*4 + c))*HQP + 4*oy + r)*HQP + x];
    }
    __syncthreads();
    // 4 ch x 25 p x 2 halves = 200 rows, each 48 uint32 (96 m values)
    for (int e = t; e < 200*48; e += 256) {
        int row = e / 48, u = e % 48;
        int c = row / 50, rem = row % 50;
        int half = rem / 25, p = rem % 25;
        int i = p / 5, j = p % 5;
        float v0 = sq[c][i][8*u + j];
        float v1 = sq[c][i][8*u + 4 + j];
        __nv_bfloat16 h0 = __float2bfloat16(v0);
        __nv_bfloat16 h1 = __float2bfloat16(v1);
        uint32_t pack;
        if (half == 0) {
            pack = (uint32_t)__bfloat16_as_ushort(h0) |
                   ((uint32_t)__bfloat16_as_ushort(h1) << 16);
        } else {
            __nv_bfloat16 l0 = __float2bfloat16(v0 - __bfloat162float(h0));
            __nv_bfloat16 l1 = __float2bfloat16(v1 - __bfloat162float(h1));
            pack = (uint32_t)__bfloat16_as_ushort(l0) |
                   ((uint32_t)__bfloat16_as_ushort(l1) << 16);
        }
        size_t krow = (size_t)n*KROW + half*KHALF + (cg*4 + c)*PP + p;
        reinterpret_cast<uint32_t*>(g_A)[krow*(MTOT/2) + oy*48 + u] = pack;
    }
}

// ---------------- keys -> bf16 hi/lo B matrix [n][l][k] ---------------------------
__global__ void build_b() {
    int n = blockIdx.x >> 6, c = blockIdx.x & 63;
    int l = threadIdx.x;  // 576
    const float* src = g_K + ((size_t)(n*MID + c))*PP*LTOT + l;
    __nv_bfloat16* dst = g_B + ((size_t)(n*LTOT) + l)*KROW + c*PP;
#pragma unroll
    for (int p = 0; p < PP; p++) {
        float v = src[(size_t)p*LTOT];
        __nv_bfloat16 h = __float2bfloat16(v);
        dst[p] = h;
        dst[KHALF + p] = __float2bfloat16(v - __bfloat162float(h));
    }
}

// ---------------- mma.sync bf16x3 scores GEMM -------------------------------------
// D[128m x 192n] = sum over 3 regions of A-slab * B-slab^T; 8 warps (2m x 4n),
// warp tile 64x48, k-chunks of 64 double-buffered via cp.async.
#define SM_STAGE 40960      // A 16KB + B 24KB
#define SM_TOTAL (2*SM_STAGE)

__global__ void __launch_bounds__(256, 1) scores_mma() {
    extern __shared__ __align__(1024) char smem[];
    const int t = threadIdx.x, lane = t & 31, wid = t >> 5;
    const int wm = wid >> 2, wn = wid & 3;
    const int mtile = blockIdx.x, ntile = blockIdx.y, n = blockIdx.z;
    const uint32_t sb = smem_u32(smem);

    const __nv_bfloat16* Abase = g_A + (size_t)n*KROW*MTOT + mtile*GM_M;
    const __nv_bfloat16* Bbase = g_B + ((size_t)n*LTOT + ntile*GM_N)*KROW;

    float acc[4][6][4];
#pragma unroll
    for (int a = 0; a < 4; a++)
#pragma unroll
        for (int b = 0; b < 6; b++)
#pragma unroll
            for (int c = 0; c < 4; c++) acc[a][b][c] = 0.f;

    auto issue_chunk = [&](int kk, int s) {
        int kr = kk < 25 ? kk : (kk < 50 ? kk - 25 : kk - 50);
        int ka = kr*64 + ((kk >= 25 && kk < 50) ? KHALF : 0);
        int kb = kr*64 + ((kk >= 50) ? KHALF : 0);
        uint32_t As = sb + s*SM_STAGE;
        uint32_t Bs = As + 16384;
        // A: 64 k-rows x 256B
#pragma unroll
        for (int e = 0; e < 4; e++) {
            int idx = t + e*256;
            int row = idx >> 4, col = idx & 15;
            uint32_t off = (uint32_t)row*256 + col*16;
            cp16(As + SWZA(off), Abase + (size_t)(ka + row)*MTOT + col*8);
        }
        // B: 192 l-rows x 128B
#pragma unroll
        for (int e = 0; e < 6; e++) {
            int idx = t + e*256;
            int row = idx >> 3, col = idx & 7;
            uint32_t off = (uint32_t)row*128 + col*16;
            cp16(Bs + SWZB(off), Bbase + (size_t)row*KROW + kb + col*8);
        }
        asm volatile("cp.async.commit_group;");
    };

    issue_chunk(0, 0);
    asm volatile("cp.async.wait_group 0;");
    __syncthreads();

    for (int kk = 0; kk < NCHUNK; kk++) {
        int s = kk & 1;
        if (kk < NCHUNK-1) issue_chunk(kk + 1, s ^ 1);

        uint32_t As = sb + s*SM_STAGE;
        uint32_t Bs = As + 16384;
#pragma unroll
        for (int st = 0; st < 4; st++) {          // 4 x k16
            uint32_t a[4][4];
            int krow = st*16 + (lane & 7) + ((lane >> 4) & 1)*8;
            int mhalf = (lane >> 3) & 1;
#pragma unroll
            for (int mi = 0; mi < 4; mi++) {
                uint32_t off = (uint32_t)krow*256 + (wm*64 + mi*16 + mhalf*8)*2;
                ldsm4t(a[mi], As + SWZA(off));
            }
            uint32_t b[3][4];
            int kbyte = st*32 + (lane >> 4)*16;
#pragma unroll
            for (int nj = 0; nj < 3; nj++) {
                uint32_t off = (uint32_t)(wn*48 + nj*16 + (lane & 15))*128 + kbyte;
                ldsm4(b[nj], Bs + SWZB(off));
            }
#pragma unroll
            for (int mi = 0; mi < 4; mi++)
#pragma unroll
                for (int ni = 0; ni < 6; ni++) {
                    int nj = ni >> 1;
                    if (ni & 1) mma_bf16(acc[mi][ni], a[mi], b[nj][1], b[nj][3]);
                    else        mma_bf16(acc[mi][ni], a[mi], b[nj][0], b[nj][2]);
                }
        }
        if (kk < NCHUNK-1) asm volatile("cp.async.wait_group 0;");
        __syncthreads();
    }

    // epilogue: write f32 scores
    int mbase = mtile*GM_M + wm*64 + (lane >> 2);
    int nbase = ntile*GM_N + wn*48 + (lane & 3)*2;
#pragma unroll
    for (int mi = 0; mi < 4; mi++)
#pragma unroll
        for (int ni = 0; ni < 6; ni++) {
            int m0 = mbase + mi*16;
            int nc = nbase + ni*8;
            float* r0 = g_attn + ((size_t)n*QPOS + m0)*LTOT + nc;
            float* r1 = r0 + 8*LTOT;
            *reinterpret_cast<float2*>(r0) = make_float2(acc[mi][ni][0], acc[mi][ni][1]);
            *reinterpret_cast<float2*>(r1) = make_float2(acc[mi][ni][2], acc[mi][ni][3]);
        }
}

// ---------------- softmax over 576 keys ------------------------------------------
__global__ void softmax_kernel() {
    int w    = threadIdx.x >> 5;
    int lane = threadIdx.x & 31;
    int gw = blockIdx.x * 8 + w;
    int n = gw / QPOS;
    float scale = g_scale[n];
    float* row = g_attn + (size_t)gw * LTOT;
    float v[18];
    float m = -1e30f;
#pragma unroll
    for (int k = 0; k < 18; k++) {
        v[k] = row[lane + 32*k] * scale;
        m = fmaxf(m, v[k]);
    }
#pragma unroll
    for (int o = 16; o; o >>= 1) m = fmaxf(m, __shfl_xor_sync(0xffffffffu, m, o));
    float s = 0.f;
#pragma unroll
    for (int k = 0; k < 18; k++) { v[k] = __expf(v[k] - m); s += v[k]; }
#pragma unroll
    for (int o = 16; o; o >>= 1) s += __shfl_xor_sync(0xffffffffu, s, o);
    float inv = 1.f / s;
#pragma unroll
    for (int k = 0; k < 18; k++) row[lane + 32*k] = v[k] * inv;
}

// ---------------- conv_transpose (stride 4, kernel 5), gather form ----------------
__device__ __forceinline__ float dot576(const float* a_sh, const float* b_g) {
    const float4* a4 = reinterpret_cast<const float4*>(a_sh);
    const float4* b4 = reinterpret_cast<const float4*>(b_g);
    float s = 0.f;
#pragma unroll 8
    for (int k = 0; k < 144; k++) {
        float4 x = a4[k];
        float4 y = __ldg(&b4[k]);
        s += x.x*y.x + x.y*y.y + x.z*y.z + x.w*y.w;
    }
    return s;
}

__global__ void conv_transpose_kernel() {
    __shared__ __align__(16) float sA[2][9][580];
    int n  = blockIdx.z;
    int y  = blockIdx.y;
    int x0 = blockIdx.x * 32;
    int t  = threadIdx.x;

    int r   = y & 3;
    int oyA = y >> 2;
    bool vA = (oyA < QW);
    int oyB = oyA - 1;
    bool vB = (r == 0) && (oyB >= 0);

    int oxlo = x0/4 - 1; if (oxlo < 0) oxlo = 0;
    int oxhi = x0/4 + 7; if (oxhi > 95) oxhi = 95;
    int nox = oxhi - oxlo + 1;

    for (int e = t; e < nox*LTOT; e += 256) {
        int o = e / LTOT, ll = e % LTOT;
        int ox = oxlo + o;
        if (vA) sA[0][o][ll] = g_attn[((size_t)n*QPOS + oyA*QW + ox)*LTOT + ll];
        if (vB) sA[1][o][ll] = g_attn[((size_t)n*QPOS + oyB*QW + ox)*LTOT + ll];
    }
    __syncthreads();

    int b = t >> 5;
    int x = x0 + (t & 31);
    if (x >= HQP) return;
    int xr  = x & 3;
    int ox1 = x >> 2;
    float acc = 0.f;
    const float* vbase = g_vT + ((size_t)n*BAND + b)*PP*LTOT;
#pragma unroll
    for (int si = 0; si < 2; si++) {
        int ii  = (si == 0) ? r : 4;
        bool sv = (si == 0) ? vA : vB;
        if (!sv) continue;
        if (ox1 < QW)
            acc += dot576(&sA[si][ox1 - oxlo][0],     vbase + (ii*5 + xr)*LTOT);
        if (xr == 0 && ox1 >= 1)
            acc += dot576(&sA[si][ox1 - 1 - oxlo][0], vbase + (ii*5 + 4)*LTOT);
    }
    g_res[(((size_t)n*BAND + b)*HQP + y)*HQP + x] = acc * (1.f/6.f);
}

// ---------------- launch -----------------------------------------------------------
extern "C" void kernel_launch(void* const* d_in, const int* in_sizes, int n_in,
                              void* d_out, int out_size) {
    const float* ms   = (const float*)d_in[0];
    const float* pan  = (const float*)d_in[1];
    const float* pan2 = (const float*)d_in[2];
    const float* wq = (const float*)d_in[3];
    const float* bq = (const float*)d_in[4];
    const float* wk = (const float*)d_in[5];
    const float* bk = (const float*)d_in[6];
    const float* wv = (const float*)d_in[7];
    const float* bv = (const float*)d_in[8];
    const float* wr = (const float*)d_in[9];
    const float* br = (const float*)d_in[10];
    float* out = (float*)d_out;

    void* pv;
    cudaGetSymbolAddress(&pv, g_kfea); float* kfea = (float*)pv;
    cudaGetSymbolAddress(&pv, g_qfea); float* qfea = (float*)pv;
    cudaGetSymbolAddress(&pv, g_vfea); float* vfea = (float*)pv;
    cudaGetSymbolAddress(&pv, g_res);  float* res  = (float*)pv;

    cudaFuncSetAttribute(scores_mma, cudaFuncAttributeMaxDynamicSharedMemorySize, SM_TOTAL);

    // feature convs
    conv_1toC<MID, HS, HS>  <<<dim3((HS*HS   + 255)/256, NB), 256>>>(pan2, wk, bk, kfea);
    conv_1toC<MID, HQ, HQP> <<<dim3((HQP*HQP + 255)/256, NB), 256>>>(pan,  wq, bq, qfea);
    conv_CtoC<BAND, HS>     <<<dim3((BAND*HS*HS + 255)/256, NB), 256>>>(ms, wv, bv, vfea);

    // patch gathers + norm scale + bf16 operand builds
    gather_k<<<NB*MID*PP,  LTOT>>>();
    gather_v<<<NB*BAND*PP, LTOT>>>();
    ssq_kernel<<<NB, LTOT>>>();
    max_kernel<<<NB, LTOT>>>();
    build_b<<<NB*MID, LTOT>>>();
    im2col_q<<<dim3(QW, 16, NB), 256>>>();

    // attention
    scores_mma<<<dim3(MTOT/GM_M, LTOT/GM_N, NB), 256, SM_TOTAL>>>();
    softmax_kernel<<<NB*QPOS/8, 256>>>();
    conv_transpose_kernel<<<dim3(13, HQP, NB), 256>>>();

    // final conv
    conv_CtoC<BAND, HQP><<<dim3((BAND*HQP*HQP + 255)/256, NB), 256>>>(res, wr, br, out);
}

// round 5
// speedup vs baseline: 3.9391x; 2.4242x over previous
#include <cuda_runtime.h>
#include <cuda_bf16.h>
#include <cstdint>

#define NB 2
#define MID 64
#define BAND 8
#define HS 96
#define HQ 384
#define HQP 385
#define LTOT 576
#define PP 25
#define QW 96
#define QPOS (QW*QW)

// scores GEMM tiling
#define GM_M 128
#define GM_N 192
#define KHALF 1600
#define KROW 3200
#define NCHUNK 75
#define MTOT 9216

// out GEMM (attn x v) tiling
#define G2_M 128
#define G2_N 256
#define AK 1152             // bf16 row: hi 576 | lo 576
#define G2_NCHUNK 27        // 3 regions x 9 chunks of 64
#define G2_SMA 16384
#define G2_SMB 32768
#define G2_STAGE (G2_SMA + G2_SMB)
#define G2_TOTAL (2*G2_STAGE)

// ---------------- scratch (device globals; no runtime allocation) ------------
__device__ float g_kfea[NB*MID*HS*HS];
__device__ float g_qfea[NB*MID*HQP*HQP];      // padded (row/col 384 = 0)
__device__ float g_vfea[NB*BAND*HS*HS];
__device__ float g_K[NB*MID*PP*LTOT];         // [n][c][p][l]
__device__ float g_scale[NB];
__device__ float g_attn[NB*QPOS*LTOT];        // f32 scores (pre-softmax)
__device__ float g_res[NB*BAND*HQP*HQP];
__device__ __nv_bfloat16 g_A[(size_t)NB*KROW*MTOT];   // 118 MB, k-major [n][k][m]
__device__ __nv_bfloat16 g_B[(size_t)NB*LTOT*KROW];   // [n][l][hi|lo]
__device__ __nv_bfloat16 g_attnb[(size_t)NB*QPOS*AK]; // softmaxed attn bf16 hi|lo
__device__ __nv_bfloat16 g_vb[(size_t)NB*G2_N*AK];    // [n][b*25+p][hi|lo], rows 200..255 stay 0
__device__ float g_out2[(size_t)NB*QPOS*G2_N];        // 18.9 MB

__device__ __forceinline__ float lrelu(float v) { return v > 0.f ? v : 0.01f * v; }

__device__ __forceinline__ uint32_t smem_u32(const void* p) {
    uint32_t a;
    asm("{ .reg .u64 t; cvta.to.shared.u64 t, %1; cvt.u32.u64 %0, t; }" : "=r"(a) : "l"(p));
    return a;
}
__device__ __forceinline__ void cp16(uint32_t dst, const void* src) {
    asm volatile("cp.async.cg.shared.global [%0], [%1], 16;" :: "r"(dst), "l"(src));
}
__device__ __forceinline__ void ldsm4(uint32_t* r, uint32_t a) {
    asm volatile("ldmatrix.sync.aligned.m8n8.x4.shared.b16 {%0,%1,%2,%3}, [%4];"
                 : "=r"(r[0]), "=r"(r[1]), "=r"(r[2]), "=r"(r[3]) : "r"(a));
}
__device__ __forceinline__ void ldsm4t(uint32_t* r, uint32_t a) {
    asm volatile("ldmatrix.sync.aligned.m8n8.x4.trans.shared.b16 {%0,%1,%2,%3}, [%4];"
                 : "=r"(r[0]), "=r"(r[1]), "=r"(r[2]), "=r"(r[3]) : "r"(a));
}
__device__ __forceinline__ void mma_bf16(float* c, const uint32_t* a, uint32_t b0, uint32_t b1) {
    asm volatile("mma.sync.aligned.m16n8k16.row.col.f32.bf16.bf16.f32 "
                 "{%0,%1,%2,%3}, {%4,%5,%6,%7}, {%8,%9}, {%0,%1,%2,%3};"
                 : "+f"(c[0]), "+f"(c[1]), "+f"(c[2]), "+f"(c[3])
                 : "r"(a[0]), "r"(a[1]), "r"(a[2]), "r"(a[3]), "r"(b0), "r"(b1));
}
#define SWZB(o) ((o) ^ (((o) >> 3) & 0x70))           // 128B rows
#define SWZA(o) ((o) ^ ((((o) >> 8) & 7) << 4))       // 256B rows

// ---------------- 3x3 conv, 1 -> C channels -----------------------------------
template<int C, int HIN, int HOUT>
__global__ void conv_1toC(const float* __restrict__ in, const float* __restrict__ w,
                          const float* __restrict__ bias, float* __restrict__ out) {
    __shared__ float sw[C*9];
    __shared__ float sb[C];
    int t = threadIdx.x;
    for (int e = t; e < C*9; e += blockDim.x) sw[e] = w[e];
    for (int e = t; e < C;   e += blockDim.x) sb[e] = bias[e];
    __syncthreads();
    int idx = blockIdx.x * blockDim.x + t;
    int n = blockIdx.y;
    if (idx >= HOUT*HOUT) return;
    int y = idx / HOUT, x = idx % HOUT;
    bool inside = (y < HIN) && (x < HIN);
    float v[9];
#pragma unroll
    for (int dy = 0; dy < 3; dy++)
#pragma unroll
        for (int dx = 0; dx < 3; dx++) {
            int yy = y + dy - 1, xx = x + dx - 1;
            v[dy*3+dx] = (inside && yy >= 0 && yy < HIN && xx >= 0 && xx < HIN)
                         ? in[(n*HIN + yy)*HIN + xx] : 0.f;
        }
#pragma unroll 8
    for (int c = 0; c < C; c++) {
        float s = 0.f;
        if (inside) {
            s = sb[c];
#pragma unroll
            for (int k = 0; k < 9; k++) s += v[k] * sw[c*9 + k];
            s = lrelu(s);
        }
        out[((n*C + c)*HOUT + y)*HOUT + x] = s;
    }
}

// ---------------- 3x3 conv, C -> C channels ------------------------------------
template<int C, int H>
__global__ void conv_CtoC(const float* __restrict__ in, const float* __restrict__ w,
                          const float* __restrict__ bias, float* __restrict__ out) {
    __shared__ float sw[C*C*9];
    __shared__ float sb[C];
    int t = threadIdx.x;
    for (int e = t; e < C*C*9; e += blockDim.x) sw[e] = w[e];
    for (int e = t; e < C;     e += blockDim.x) sb[e] = bias[e];
    __syncthreads();
    int idx = blockIdx.x * blockDim.x + t;
    int n = blockIdx.y;
    if (idx >= C*H*H) return;
    int co  = idx / (H*H);
    int pix = idx % (H*H);
    int y = pix / H, x = pix % H;
    float s = sb[co];
    for (int ci = 0; ci < C; ci++) {
        const float* ip = in + ((size_t)(n*C + ci))*H*H;
#pragma unroll
        for (int dy = 0; dy < 3; dy++) {
            int yy = y + dy - 1;
            if (yy < 0 || yy >= H) continue;
#pragma unroll
            for (int dx = 0; dx < 3; dx++) {
                int xx = x + dx - 1;
                if (xx < 0 || xx >= H) continue;
                s += __ldg(&ip[yy*H + xx]) * sw[(co*C + ci)*9 + dy*3 + dx];
            }
        }
    }
    out[((size_t)(n*C + co)*H + y)*H + x] = lrelu(s);
}

// ---------------- gather K patches; V patches straight to bf16 hi/lo ------------
__global__ void gather_k() {
    int bid = blockIdx.x;
    int n  = bid / (MID*PP);
    int cp = bid % (MID*PP);
    int c  = cp / PP;
    int p  = cp % PP;
    int i  = p / 5, j = p % 5;
    int l  = threadIdx.x;
    int py = l / 24, px = l % 24;
    int sy = 4*py + i - 2; if (sy < 0) sy += 97;
    int sx = 4*px + j - 2; if (sx < 0) sx += 97;
    float v = 0.f;
    if (sy < HS && sx < HS)
        v = g_kfea[((n*MID + c)*HS + sy)*HS + sx];
    g_K[(size_t)bid*LTOT + l] = v;
}

__global__ void gather_v() {
    int bid = blockIdx.x;                 // n*200 + b*25 + p
    int n  = bid / (BAND*PP);
    int bp = bid % (BAND*PP);
    int b  = bp / PP;
    int p  = bp % PP;
    int i  = p / 5, j = p % 5;
    int l  = threadIdx.x;
    int py = l / 24, px = l % 24;
    int sy = 4*py + i - 2; if (sy < 0) sy += 97;
    int sx = 4*px + j - 2; if (sx < 0) sx += 97;
    float v = 0.f;
    if (sy < HS && sx < HS)
        v = g_vfea[((n*BAND + b)*HS + sy)*HS + sx];
    __nv_bfloat16 h = __float2bfloat16(v);
    __nv_bfloat16* dst = g_vb + ((size_t)(n*G2_N) + bp)*AK;
    dst[l] = h;
    dst[LTOT + l] = __float2bfloat16(v - __bfloat162float(h));
}

// ---------------- ssq + max fused -----------------------------------------------
__global__ void ssqmax_kernel() {
    __shared__ float red[LTOT];
    int n = blockIdx.x;
    int l = threadIdx.x;
    const float* base = g_K + (size_t)n*MID*PP*LTOT + l;
    float s = 0.f;
#pragma unroll 4
    for (int e = 0; e < MID*PP; e++) {
        float v = base[(size_t)e*LTOT];
        s += v*v;
    }
    red[l] = s;
    __syncthreads();
    if (l < 64) red[l] = fmaxf(red[l], red[l + 512]);
    __syncthreads();
    for (int st = 256; st >= 1; st >>= 1) {
        if (l < st) red[l] = fmaxf(red[l], red[l + st]);
        __syncthreads();
    }
    if (l == 0) g_scale[n] = 10.f / sqrtf(red[0]);
}

// ---------------- im2col Q -> k-major bf16 A (hi|lo) -----------------------------
__global__ void im2col_q() {
    __shared__ float sq[4][5][388];
    int oy = blockIdx.x;
    int cg = blockIdx.y;
    int n  = blockIdx.z;
    int t  = threadIdx.x;
    for (int e = t; e < 4*5*385; e += 256) {
        int c = e / 1925, rem = e % 1925, r = rem / 385, x = rem % 385;
        sq[c][r][x] = g_qfea[(((size_t)(n*MID + cg*4 + c))*HQP + 4*oy + r)*HQP + x];
    }
    __syncthreads();
    for (int e = t; e < 200*48; e += 256) {
        int row = e / 48, u = e % 48;
        int c = row / 50, rem = row % 50;
        int half = rem / 25, p = rem % 25;
        int i = p / 5, j = p % 5;
        float v0 = sq[c][i][8*u + j];
        float v1 = sq[c][i][8*u + 4 + j];
        __nv_bfloat16 h0 = __float2bfloat16(v0);
        __nv_bfloat16 h1 = __float2bfloat16(v1);
        uint32_t pack;
        if (half == 0) {
            pack = (uint32_t)__bfloat16_as_ushort(h0) |
                   ((uint32_t)__bfloat16_as_ushort(h1) << 16);
        } else {
            __nv_bfloat16 l0 = __float2bfloat16(v0 - __bfloat162float(h0));
            __nv_bfloat16 l1 = __float2bfloat16(v1 - __bfloat162float(h1));
            pack = (uint32_t)__bfloat16_as_ushort(l0) |
                   ((uint32_t)__bfloat16_as_ushort(l1) << 16);
        }
        size_t krow = (size_t)n*KROW + half*KHALF + (cg*4 + c)*PP + p;
        reinterpret_cast<uint32_t*>(g_A)[krow*(MTOT/2) + oy*48 + u] = pack;
    }
}

// ---------------- keys -> bf16 hi/lo B matrix [n][l][k] ---------------------------
__global__ void build_b() {
    int n = blockIdx.x >> 6, c = blockIdx.x & 63;
    int l = threadIdx.x;
    const float* src = g_K + ((size_t)(n*MID + c))*PP*LTOT + l;
    __nv_bfloat16* dst = g_B + ((size_t)(n*LTOT) + l)*KROW + c*PP;
#pragma unroll
    for (int p = 0; p < PP; p++) {
        float v = src[(size_t)p*LTOT];
        __nv_bfloat16 h = __float2bfloat16(v);
        dst[p] = h;
        dst[KHALF + p] = __float2bfloat16(v - __bfloat162float(h));
    }
}

// ---------------- mma.sync bf16x3 scores GEMM -------------------------------------
#define SM_STAGE 40960
#define SM_TOTAL (2*SM_STAGE)

__global__ void __launch_bounds__(256, 1) scores_mma() {
    extern __shared__ __align__(1024) char smem[];
    const int t = threadIdx.x, lane = t & 31, wid = t >> 5;
    const int wm = wid >> 2, wn = wid & 3;
    const int ntile = blockIdx.x, mtile = blockIdx.y, n = blockIdx.z;
    const uint32_t sb = smem_u32(smem);

    const __nv_bfloat16* Abase = g_A + (size_t)n*KROW*MTOT + mtile*GM_M;
    const __nv_bfloat16* Bbase = g_B + ((size_t)n*LTOT + ntile*GM_N)*KROW;

    float acc[4][6][4];
#pragma unroll
    for (int a = 0; a < 4; a++)
#pragma unroll
        for (int b = 0; b < 6; b++)
#pragma unroll
            for (int c = 0; c < 4; c++) acc[a][b][c] = 0.f;

    auto issue_chunk = [&](int kk, int s) {
        int kr = kk < 25 ? kk : (kk < 50 ? kk - 25 : kk - 50);
        int ka = kr*64 + ((kk >= 25 && kk < 50) ? KHALF : 0);
        int kb = kr*64 + ((kk >= 50) ? KHALF : 0);
        uint32_t As = sb + s*SM_STAGE;
        uint32_t Bs = As + 16384;
#pragma unroll
        for (int e = 0; e < 4; e++) {
            int idx = t + e*256;
            int row = idx >> 4, col = idx & 15;
            uint32_t off = (uint32_t)row*256 + col*16;
            cp16(As + SWZA(off), Abase + (size_t)(ka + row)*MTOT + col*8);
        }
#pragma unroll
        for (int e = 0; e < 6; e++) {
            int idx = t + e*256;
            int row = idx >> 3, col = idx & 7;
            uint32_t off = (uint32_t)row*128 + col*16;
            cp16(Bs + SWZB(off), Bbase + (size_t)row*KROW + kb + col*8);
        }
        asm volatile("cp.async.commit_group;");
    };

    issue_chunk(0, 0);
    asm volatile("cp.async.wait_group 0;");
    __syncthreads();

    for (int kk = 0; kk < NCHUNK; kk++) {
        int s = kk & 1;
        if (kk < NCHUNK-1) issue_chunk(kk + 1, s ^ 1);

        uint32_t As = sb + s*SM_STAGE;
        uint32_t Bs = As + 16384;
#pragma unroll
        for (int st = 0; st < 4; st++) {
            uint32_t a[4][4];
            int krow = st*16 + (lane & 7) + ((lane >> 4) & 1)*8;
            int mhalf = (lane >> 3) & 1;
#pragma unroll
            for (int mi = 0; mi < 4; mi++) {
                uint32_t off = (uint32_t)krow*256 + (wm*64 + mi*16 + mhalf*8)*2;
                ldsm4t(a[mi], As + SWZA(off));
            }
            uint32_t b[3][4];
            int kbyte = st*32 + (lane >> 4)*16;
#pragma unroll
            for (int nj = 0; nj < 3; nj++) {
                uint32_t off = (uint32_t)(wn*48 + nj*16 + (lane & 15))*128 + kbyte;
                ldsm4(b[nj], Bs + SWZB(off));
            }
#pragma unroll
            for (int mi = 0; mi < 4; mi++)
#pragma unroll
                for (int ni = 0; ni < 6; ni++) {
                    int nj = ni >> 1;
                    if (ni & 1) mma_bf16(acc[mi][ni], a[mi], b[nj][1], b[nj][3]);
                    else        mma_bf16(acc[mi][ni], a[mi], b[nj][0], b[nj][2]);
                }
        }
        if (kk < NCHUNK-1) asm volatile("cp.async.wait_group 0;");
        __syncthreads();
    }

    int mbase = mtile*GM_M + wm*64 + (lane >> 2);
    int nbase = ntile*GM_N + wn*48 + (lane & 3)*2;
#pragma unroll
    for (int mi = 0; mi < 4; mi++)
#pragma unroll
        for (int ni = 0; ni < 6; ni++) {
            int m0 = mbase + mi*16;
            int nc = nbase + ni*8;
            float* r0 = g_attn + ((size_t)n*QPOS + m0)*LTOT + nc;
            float* r1 = r0 + 8*LTOT;
            *reinterpret_cast<float2*>(r0) = make_float2(acc[mi][ni][0], acc[mi][ni][1]);
            *reinterpret_cast<float2*>(r1) = make_float2(acc[mi][ni][2], acc[mi][ni][3]);
        }
}

// ---------------- softmax over 576 keys -> bf16 hi/lo attn -------------------------
__global__ void softmax_kernel() {
    int w    = threadIdx.x >> 5;
    int lane = threadIdx.x & 31;
    int gw = blockIdx.x * 8 + w;
    int n = gw / QPOS;
    float scale = g_scale[n];
    const float* row = g_attn + (size_t)gw * LTOT;
    __nv_bfloat16* rowb = g_attnb + (size_t)gw * AK;
    float v[18];
    float m = -1e30f;
#pragma unroll
    for (int k = 0; k < 18; k++) {
        v[k] = row[lane + 32*k] * scale;
        m = fmaxf(m, v[k]);
    }
#pragma unroll
    for (int o = 16; o; o >>= 1) m = fmaxf(m, __shfl_xor_sync(0xffffffffu, m, o));
    float s = 0.f;
#pragma unroll
    for (int k = 0; k < 18; k++) { v[k] = __expf(v[k] - m); s += v[k]; }
#pragma unroll
    for (int o = 16; o; o >>= 1) s += __shfl_xor_sync(0xffffffffu, s, o);
    float inv = 1.f / s;
#pragma unroll
    for (int k = 0; k < 18; k++) {
        float val = v[k] * inv;
        __nv_bfloat16 h = __float2bfloat16(val);
        rowb[lane + 32*k] = h;
        rowb[LTOT + lane + 32*k] = __float2bfloat16(val - __bfloat162float(h));
    }
}

// ---------------- out GEMM: out2[m][200] = attn[m][:] x vb^T ------------------------
__global__ void __launch_bounds__(256, 1) out_mma() {
    extern __shared__ __align__(1024) char smem[];
    const int t = threadIdx.x, lane = t & 31, wid = t >> 5;
    const int wm = wid >> 1, wn = wid & 1;
    const int mtile = blockIdx.x, n = blockIdx.z;
    const uint32_t sb = smem_u32(smem);

    const __nv_bfloat16* Abase = g_attnb + ((size_t)n*QPOS + mtile*G2_M)*AK;
    const __nv_bfloat16* Bbase = g_vb + (size_t)n*G2_N*AK;

    float acc[2][16][4];
#pragma unroll
    for (int a = 0; a < 2; a++)
#pragma unroll
        for (int b = 0; b < 16; b++)
#pragma unroll
            for (int c = 0; c < 4; c++) acc[a][b][c] = 0.f;

    auto issue_chunk = [&](int kk, int s) {
        int ka, kb;
        if (kk < 9)       { ka = kk*64;                kb = kk*64; }
        else if (kk < 18) { ka = LTOT + (kk-9)*64;     kb = (kk-9)*64; }
        else              { ka = (kk-18)*64;           kb = LTOT + (kk-18)*64; }
        uint32_t As = sb + s*G2_STAGE;
        uint32_t Bs = As + G2_SMA;
#pragma unroll
        for (int e = 0; e < 4; e++) {                 // A: 128 rows x 128B
            int idx = t + e*256;
            int row = idx >> 3, col = idx & 7;
            uint32_t off = (uint32_t)row*128 + col*16;
            cp16(As + SWZB(off), Abase + (size_t)row*AK + ka + col*8);
        }
#pragma unroll
        for (int e = 0; e < 8; e++) {                 // B: 256 rows x 128B
            int idx = t + e*256;
            int row = idx >> 3, col = idx & 7;
            uint32_t off = (uint32_t)row*128 + col*16;
            cp16(Bs + SWZB(off), Bbase + (size_t)row*AK + kb + col*8);
        }
        asm volatile("cp.async.commit_group;");
    };

    issue_chunk(0, 0);
    asm volatile("cp.async.wait_group 0;");
    __syncthreads();

    for (int kk = 0; kk < G2_NCHUNK; kk++) {
        int s = kk & 1;
        if (kk < G2_NCHUNK-1) issue_chunk(kk + 1, s ^ 1);

        uint32_t As = sb + s*G2_STAGE;
        uint32_t Bs = As + G2_SMA;
#pragma unroll
        for (int st = 0; st < 4; st++) {
            int kbyte = st*32 + (lane >> 4)*16;
            uint32_t a[2][4];
#pragma unroll
            for (int mi = 0; mi < 2; mi++) {
                uint32_t off = (uint32_t)(wm*32 + mi*16 + (lane & 15))*128 + kbyte;
                ldsm4(a[mi], As + SWZB(off));
            }
            uint32_t b[8][4];
#pragma unroll
            for (int nj = 0; nj < 8; nj++) {
                uint32_t off = (uint32_t)(wn*128 + nj*16 + (lane & 15))*128 + kbyte;
                ldsm4(b[nj], Bs + SWZB(off));
            }
#pragma unroll
            for (int mi = 0; mi < 2; mi++)
#pragma unroll
                for (int ni = 0; ni < 16; ni++) {
                    int nj = ni >> 1;
                    if (ni & 1) mma_bf16(acc[mi][ni], a[mi], b[nj][1], b[nj][3]);
                    else        mma_bf16(acc[mi][ni], a[mi], b[nj][0], b[nj][2]);
                }
        }
        if (kk < G2_NCHUNK-1) asm volatile("cp.async.wait_group 0;");
        __syncthreads();
    }

    int mbase = mtile*G2_M + wm*32 + (lane >> 2);
    int nbase = wn*128 + (lane & 3)*2;
#pragma unroll
    for (int mi = 0; mi < 2; mi++)
#pragma unroll
        for (int ni = 0; ni < 16; ni++) {
            int m0 = mbase + mi*16;
            int nc = nbase + ni*8;
            float* r0 = g_out2 + ((size_t)n*QPOS + m0)*G2_N + nc;
            float* r1 = r0 + 8*G2_N;
            *reinterpret_cast<float2*>(r0) = make_float2(acc[mi][ni][0], acc[mi][ni][1]);
            *reinterpret_cast<float2*>(r1) = make_float2(acc[mi][ni][2], acc[mi][ni][3]);
        }
}

// ---------------- scatter: out2 -> res (conv_transpose geometry) --------------------
__global__ void scatter_out() {
    int idx = blockIdx.x * 256 + threadIdx.x;
    int n = blockIdx.y;
    if (idx >= HQP*HQP) return;
    int y = idx / HQP, x = idx % HQP;
    int oyA = y >> 2, iA = y & 3;  bool vA = oyA < QW;
    int oyB = oyA - 1;             bool vB = (iA == 0) && (oyB >= 0);
    int oxA = x >> 2, jA = x & 3;  bool hA = oxA < QW;
    int oxB = oxA - 1;             bool hB = (jA == 0) && (oxB >= 0);

    float acc[BAND];
#pragma unroll
    for (int b = 0; b < BAND; b++) acc[b] = 0.f;

    const float* base = g_out2 + (size_t)n*QPOS*G2_N;
#pragma unroll
    for (int ti = 0; ti < 2; ti++) {
        bool vi = ti ? vB : vA;
        if (!vi) continue;
        int oy = ti ? oyB : oyA;
        int ii = ti ? 4 : iA;
#pragma unroll
        for (int tj = 0; tj < 2; tj++) {
            bool vj = tj ? hB : hA;
            if (!vj) continue;
            int ox = tj ? oxB : oxA;
            int jj = tj ? 4 : jA;
            const float* row = base + (size_t)(oy*QW + ox)*G2_N + ii*5 + jj;
#pragma unroll
            for (int b = 0; b < BAND; b++) acc[b] += __ldg(&row[b*PP]);
        }
    }
#pragma unroll
    for (int b = 0; b < BAND; b++)
        g_res[(((size_t)n*BAND + b)*HQP + y)*HQP + x] = acc[b] * (1.f/6.f);
}

// ---------------- launch -----------------------------------------------------------
extern "C" void kernel_launch(void* const* d_in, const int* in_sizes, int n_in,
                              void* d_out, int out_size) {
    const float* ms   = (const float*)d_in[0];
    const float* pan  = (const float*)d_in[1];
    const float* pan2 = (const float*)d_in[2];
    const float* wq = (const float*)d_in[3];
    const float* bq = (const float*)d_in[4];
    const float* wk = (const float*)d_in[5];
    const float* bk = (const float*)d_in[6];
    const float* wv = (const float*)d_in[7];
    const float* bv = (const float*)d_in[8];
    const float* wr = (const float*)d_in[9];
    const float* br = (const float*)d_in[10];
    float* out = (float*)d_out;

    void* pv;
    cudaGetSymbolAddress(&pv, g_kfea); float* kfea = (float*)pv;
    cudaGetSymbolAddress(&pv, g_qfea); float* qfea = (float*)pv;
    cudaGetSymbolAddress(&pv, g_vfea); float* vfea = (float*)pv;
    cudaGetSymbolAddress(&pv, g_res);  float* res  = (float*)pv;

    cudaFuncSetAttribute(scores_mma, cudaFuncAttributeMaxDynamicSharedMemorySize, SM_TOTAL);
    cudaFuncSetAttribute(out_mma,    cudaFuncAttributeMaxDynamicSharedMemorySize, G2_TOTAL);

    // feature convs
    conv_1toC<MID, HS, HS>  <<<dim3((HS*HS   + 255)/256, NB), 256>>>(pan2, wk, bk, kfea);
    conv_1toC<MID, HQ, HQP> <<<dim3((HQP*HQP + 255)/256, NB), 256>>>(pan,  wq, bq, qfea);
    conv_CtoC<BAND, HS>     <<<dim3((BAND*HS*HS + 255)/256, NB), 256>>>(ms, wv, bv, vfea);

    // patch gathers + norm scale + bf16 operand builds
    gather_k<<<NB*MID*PP,  LTOT>>>();
    gather_v<<<NB*BAND*PP, LTOT>>>();
    ssqmax_kernel<<<NB, LTOT>>>();
    build_b<<<NB*MID, LTOT>>>();
    im2col_q<<<dim3(QW, 16, NB), 256>>>();

    // attention
    scores_mma<<<dim3(LTOT/GM_N, MTOT/GM_M, NB), 256, SM_TOTAL>>>();
    softmax_kernel<<<NB*QPOS/8, 256>>>();
    out_mma<<<dim3(MTOT/G2_M, 1, NB), 256, G2_TOTAL>>>();
    scatter_out<<<dim3((HQP*HQP + 255)/256, NB), 256>>>();

    // final conv
    conv_CtoC<BAND, HQP><<<dim3((BAND*HQP*HQP + 255)/256, NB), 256>>>(res, wr, br, out);
}

// round 6
// speedup vs baseline: 4.1991x; 1.0660x over previous
#include <cuda_runtime.h>
#include <cuda_bf16.h>
#include <cstdint>

#define NB 2
#define MID 64
#define BAND 8
#define HS 96
#define HQ 384
#define HQP 385
#define LTOT 576
#define PP 25
#define QW 96
#define QPOS (QW*QW)

// scores GEMM tiling (fused im2col, joint regions)
#define GM_M 96
#define GM_N 192
#define KHALF 1600
#define KROW 3200
#define SCHUNK 25           // 25 chunks of k64, 3 region-passes each

// out GEMM (attn x v) tiling
#define G2_M 128
#define G2_N 256
#define AK 1152
#define G2_NCHUNK 27
#define G2_SMA 16384
#define G2_SMB 32768
#define G2_STAGE (G2_SMA + G2_SMB)
#define G2_TOTAL (2*G2_STAGE)

// scores smem: per stage  Ahi 12K | Alo 12K | Bhi 24K | Blo 24K
#define SC_AHI 0
#define SC_ALO 12288
#define SC_BHI 24576
#define SC_BLO 49152
#define SC_STAGE 73728
#define SC_TOTAL (2*SC_STAGE)

// ---------------- scratch (device globals; no runtime allocation) ------------
__device__ float g_kfea[NB*MID*HS*HS];
__device__ float g_qfea[NB*MID*HQP*HQP];      // padded (row/col 384 = 0)
__device__ float g_vfea[NB*BAND*HS*HS];
__device__ float g_ssq[NB*LTOT];
__device__ float g_scale[NB];
__device__ float g_attn[NB*QPOS*LTOT];        // f32 scores (pre-softmax)
__device__ float g_res[NB*BAND*HQP*HQP];
__device__ __nv_bfloat16 g_B[(size_t)NB*LTOT*KROW];   // keys [n][l][hi1600|lo1600]
__device__ __nv_bfloat16 g_attnb[(size_t)NB*QPOS*AK]; // softmaxed attn bf16 hi|lo
__device__ __nv_bfloat16 g_vb[(size_t)NB*G2_N*AK];    // [n][b*25+p][hi|lo], rows 200..255 = 0
__device__ float g_out2[(size_t)NB*QPOS*G2_N];

__device__ __forceinline__ float lrelu(float v) { return v > 0.f ? v : 0.01f * v; }

__device__ __forceinline__ uint32_t smem_u32(const void* p) {
    uint32_t a;
    asm("{ .reg .u64 t; cvta.to.shared.u64 t, %1; cvt.u32.u64 %0, t; }" : "=r"(a) : "l"(p));
    return a;
}
__device__ __forceinline__ void cp16(uint32_t dst, const void* src) {
    asm volatile("cp.async.cg.shared.global [%0], [%1], 16;" :: "r"(dst), "l"(src));
}
__device__ __forceinline__ void ldsm4(uint32_t* r, uint32_t a) {
    asm volatile("ldmatrix.sync.aligned.m8n8.x4.shared.b16 {%0,%1,%2,%3}, [%4];"
                 : "=r"(r[0]), "=r"(r[1]), "=r"(r[2]), "=r"(r[3]) : "r"(a));
}
__device__ __forceinline__ void mma_bf16(float* c, const uint32_t* a, uint32_t b0, uint32_t b1) {
    asm volatile("mma.sync.aligned.m16n8k16.row.col.f32.bf16.bf16.f32 "
                 "{%0,%1,%2,%3}, {%4,%5,%6,%7}, {%8,%9}, {%0,%1,%2,%3};"
                 : "+f"(c[0]), "+f"(c[1]), "+f"(c[2]), "+f"(c[3])
                 : "r"(a[0]), "r"(a[1]), "r"(a[2]), "r"(a[3]), "r"(b0), "r"(b1));
}
#define SWZB(o) ((o) ^ (((o) >> 3) & 0x70))   // 128B rows

// ---------------- 3x3 conv, 1 -> C channels -----------------------------------
template<int C, int HIN, int HOUT>
__global__ void conv_1toC(const float* __restrict__ in, const float* __restrict__ w,
                          const float* __restrict__ bias, float* __restrict__ out) {
    __shared__ float sw[C*9];
    __shared__ float sb[C];
    int t = threadIdx.x;
    for (int e = t; e < C*9; e += blockDim.x) sw[e] = w[e];
    for (int e = t; e < C;   e += blockDim.x) sb[e] = bias[e];
    __syncthreads();
    int idx = blockIdx.x * blockDim.x + t;
    int n = blockIdx.y;
    if (idx >= HOUT*HOUT) return;
    int y = idx / HOUT, x = idx % HOUT;
    bool inside = (y < HIN) && (x < HIN);
    float v[9];
#pragma unroll
    for (int dy = 0; dy < 3; dy++)
#pragma unroll
        for (int dx = 0; dx < 3; dx++) {
            int yy = y + dy - 1, xx = x + dx - 1;
            v[dy*3+dx] = (inside && yy >= 0 && yy < HIN && xx >= 0 && xx < HIN)
                         ? in[(n*HIN + yy)*HIN + xx] : 0.f;
        }
#pragma unroll 8
    for (int c = 0; c < C; c++) {
        float s = 0.f;
        if (inside) {
            s = sb[c];
#pragma unroll
            for (int k = 0; k < 9; k++) s += v[k] * sw[c*9 + k];
            s = lrelu(s);
        }
        out[((n*C + c)*HOUT + y)*HOUT + x] = s;
    }
}

// ---------------- 3x3 conv, C -> C channels ------------------------------------
template<int C, int H>
__global__ void conv_CtoC(const float* __restrict__ in, const float* __restrict__ w,
                          const float* __restrict__ bias, float* __restrict__ out) {
    __shared__ float sw[C*C*9];
    __shared__ float sb[C];
    int t = threadIdx.x;
    for (int e = t; e < C*C*9; e += blockDim.x) sw[e] = w[e];
    for (int e = t; e < C;     e += blockDim.x) sb[e] = bias[e];
    __syncthreads();
    int idx = blockIdx.x * blockDim.x + t;
    int n = blockIdx.y;
    if (idx >= C*H*H) return;
    int co  = idx / (H*H);
    int pix = idx % (H*H);
    int y = pix / H, x = pix % H;
    float s = sb[co];
    for (int ci = 0; ci < C; ci++) {
        const float* ip = in + ((size_t)(n*C + ci))*H*H;
#pragma unroll
        for (int dy = 0; dy < 3; dy++) {
            int yy = y + dy - 1;
            if (yy < 0 || yy >= H) continue;
#pragma unroll
            for (int dx = 0; dx < 3; dx++) {
                int xx = x + dx - 1;
                if (xx < 0 || xx >= H) continue;
                s += __ldg(&ip[yy*H + xx]) * sw[(co*C + ci)*9 + dy*3 + dx];
            }
        }
    }
    out[((size_t)(n*C + co)*H + y)*H + x] = lrelu(s);
}

// ---------------- K patches -> bf16 hi/lo B matrix (fused gather+split) ---------
__global__ void build_b_direct() {
    int n = blockIdx.x >> 6, c = blockIdx.x & 63;
    int l = threadIdx.x;                  // 576
    int py = l / 24, px = l % 24;
    __nv_bfloat16* dst = g_B + ((size_t)(n*LTOT) + l)*KROW + c*PP;
    const float* src = g_kfea + ((size_t)(n*MID + c))*HS*HS;
#pragma unroll
    for (int p = 0; p < PP; p++) {
        int i = p / 5, j = p % 5;
        int sy = 4*py + i - 2; if (sy < 0) sy += 97;
        int sx = 4*px + j - 2; if (sx < 0) sx += 97;
        float v = 0.f;
        if (sy < HS && sx < HS) v = src[sy*HS + sx];
        __nv_bfloat16 h = __float2bfloat16(v);
        dst[p] = h;
        dst[KHALF + p] = __float2bfloat16(v - __bfloat162float(h));
    }
}

// ---------------- V patches straight to bf16 hi/lo -------------------------------
__global__ void gather_v() {
    int bid = blockIdx.x;                 // n*200 + b*25 + p
    int n  = bid / (BAND*PP);
    int bp = bid % (BAND*PP);
    int b  = bp / PP;
    int p  = bp % PP;
    int i  = p / 5, j = p % 5;
    int l  = threadIdx.x;
    int py = l / 24, px = l % 24;
    int sy = 4*py + i - 2; if (sy < 0) sy += 97;
    int sx = 4*px + j - 2; if (sx < 0) sx += 97;
    float v = 0.f;
    if (sy < HS && sx < HS)
        v = g_vfea[((n*BAND + b)*HS + sy)*HS + sx];
    __nv_bfloat16 h = __float2bfloat16(v);
    __nv_bfloat16* dst = g_vb + ((size_t)(n*G2_N) + bp)*AK;
    dst[l] = h;
    dst[LTOT + l] = __float2bfloat16(v - __bfloat162float(h));
}

// ---------------- per-patch ssq from g_B (hi+lo), then max ----------------------
__global__ void ssq_b() {
    __shared__ float red[4];
    int row = blockIdx.x;                 // n*576 + l
    int t = threadIdx.x;                  // 128
    const uint4* rp = reinterpret_cast<const uint4*>(g_B + (size_t)row*KROW);
    float s = 0.f;
    for (int e = t; e < 200; e += 128) {
        uint4 hi = __ldg(&rp[e]);
        uint4 lo = __ldg(&rp[200 + e]);
        const uint32_t* hw = &hi.x;
        const uint32_t* lw = &lo.x;
#pragma unroll
        for (int q = 0; q < 4; q++) {
            float2 fh = __bfloat1622float2(*reinterpret_cast<const __nv_bfloat162*>(&hw[q]));
            float2 fl = __bfloat1622float2(*reinterpret_cast<const __nv_bfloat162*>(&lw[q]));
            float v0 = fh.x + fl.x, v1 = fh.y + fl.y;
            s += v0*v0 + v1*v1;
        }
    }
#pragma unroll
    for (int o = 16; o; o >>= 1) s += __shfl_xor_sync(0xffffffffu, s, o);
    if ((t & 31) == 0) red[t >> 5] = s;
    __syncthreads();
    if (t == 0) g_ssq[row] = red[0] + red[1] + red[2] + red[3];
}

__global__ void max_kernel() {
    __shared__ float red[LTOT];
    int n = blockIdx.x;
    int t = threadIdx.x;
    red[t] = g_ssq[n*LTOT + t];
    __syncthreads();
    if (t < 64) red[t] = fmaxf(red[t], red[t + 512]);
    __syncthreads();
    for (int s = 256; s >= 1; s >>= 1) {
        if (t < s) red[t] = fmaxf(red[t], red[t + s]);
        __syncthreads();
    }
    if (t == 0) g_scale[n] = 10.f / sqrtf(red[0]);
}

// ---------------- scores GEMM: fused im2col + bf16x3, joint-region chunks ---------
// CTA: oy row (96 queries) x 192 keys. 8 warps 2m x 4n, warp tile 48x48.
__global__ void __launch_bounds__(256, 1) scores_mma() {
    extern __shared__ __align__(1024) char smem[];
    const int t = threadIdx.x, lane = t & 31, wid = t >> 5;
    const int wm = wid >> 2, wn = wid & 3;
    const int ntile = blockIdx.x, oy = blockIdx.y, n = blockIdx.z;
    const uint32_t sb = smem_u32(smem);

    const float* Qn = g_qfea + (size_t)n*MID*HQP*HQP + (4*oy)*HQP;
    const __nv_bfloat16* Bb = g_B + ((size_t)n*LTOT + ntile*GM_N)*KROW;

    float acc[3][6][4];
#pragma unroll
    for (int a = 0; a < 3; a++)
#pragma unroll
        for (int b = 0; b < 6; b++)
#pragma unroll
            for (int c = 0; c < 4; c++) acc[a][b][c] = 0.f;

    auto stage = [&](int kr, int s) {
        char* base = smem + s*SC_STAGE;
        // A: compute hi/lo from qfea. 96 m x 32 k-pairs = 3072 u32-pair units.
#pragma unroll
        for (int it = 0; it < 12; it++) {
            int idx = it*256 + t;
            int m  = idx >> 5;
            int kp = idx & 31;
            float v0, v1;
            {
                int k = kr*64 + kp*2;
                int c = (k*41944) >> 20;      // k/25 (exact for k<1600)
                int p = k - c*25;
                int i = (p*205) >> 10;        // p/5
                int j = p - i*5;
                v0 = __ldg(&Qn[((size_t)c*HQP + i)*HQP + 4*m + j]);
                k++;
                c = (k*41944) >> 20;
                p = k - c*25;
                i = (p*205) >> 10;
                j = p - i*5;
                v1 = __ldg(&Qn[((size_t)c*HQP + i)*HQP + 4*m + j]);
            }
            __nv_bfloat16 h0 = __float2bfloat16(v0);
            __nv_bfloat16 h1 = __float2bfloat16(v1);
            __nv_bfloat16 l0 = __float2bfloat16(v0 - __bfloat162float(h0));
            __nv_bfloat16 l1 = __float2bfloat16(v1 - __bfloat162float(h1));
            uint32_t hp = (uint32_t)__bfloat16_as_ushort(h0) |
                          ((uint32_t)__bfloat16_as_ushort(h1) << 16);
            uint32_t lp = (uint32_t)__bfloat16_as_ushort(l0) |
                          ((uint32_t)__bfloat16_as_ushort(l1) << 16);
            uint32_t sw = SWZB((uint32_t)m*128 + kp*4);
            *reinterpret_cast<uint32_t*>(base + SC_AHI + sw) = hp;
            *reinterpret_cast<uint32_t*>(base + SC_ALO + sw) = lp;
        }
        // B: cp.async hi+lo, 192 rows x 128B each
        uint32_t bhi = sb + s*SC_STAGE + SC_BHI;
        uint32_t blo = sb + s*SC_STAGE + SC_BLO;
#pragma unroll
        for (int e = 0; e < 6; e++) {
            int idx = t + e*256;
            int row = idx >> 3, col = idx & 7;
            uint32_t off = SWZB((uint32_t)row*128 + col*16);
            const __nv_bfloat16* rp = Bb + (size_t)row*KROW + kr*64 + col*8;
            cp16(bhi + off, rp);
            cp16(blo + off, rp + KHALF);
        }
        asm volatile("cp.async.commit_group;");
    };

    stage(0, 0);
    asm volatile("cp.async.wait_group 0;");
    __syncthreads();

    for (int kk = 0; kk < SCHUNK; kk++) {
        int s = kk & 1;
        if (kk < SCHUNK-1) stage(kk + 1, s ^ 1);

#pragma unroll
        for (int reg = 0; reg < 3; reg++) {
            uint32_t Abase = sb + s*SC_STAGE + (reg == 1 ? SC_ALO : SC_AHI);
            uint32_t Bbase = sb + s*SC_STAGE + (reg == 2 ? SC_BLO : SC_BHI);
#pragma unroll
            for (int st = 0; st < 4; st++) {
                uint32_t col = st*32 + (lane >> 4)*16;
                uint32_t a[3][4];
#pragma unroll
                for (int mi = 0; mi < 3; mi++) {
                    uint32_t row = wm*48 + mi*16 + (lane & 15);
                    ldsm4(a[mi], Abase + SWZB(row*128 + col));
                }
                uint32_t b[3][4];
#pragma unroll
                for (int nj = 0; nj < 3; nj++) {
                    uint32_t row = wn*48 + nj*16 + (lane & 15);
                    ldsm4(b[nj], Bbase + SWZB(row*128 + col));
                }
#pragma unroll
                for (int mi = 0; mi < 3; mi++)
#pragma unroll
                    for (int ni = 0; ni < 6; ni++) {
                        int nj = ni >> 1;
                        if (ni & 1) mma_bf16(acc[mi][ni], a[mi], b[nj][1], b[nj][3]);
                        else        mma_bf16(acc[mi][ni], a[mi], b[nj][0], b[nj][2]);
                    }
            }
        }
        if (kk < SCHUNK-1) asm volatile("cp.async.wait_group 0;");
        __syncthreads();
    }

    // epilogue
    int mbase = oy*QW + wm*48 + (lane >> 2);
    int nbase = ntile*GM_N + wn*48 + (lane & 3)*2;
#pragma unroll
    for (int mi = 0; mi < 3; mi++)
#pragma unroll
        for (int ni = 0; ni < 6; ni++) {
            int m0 = mbase + mi*16;
            int nc = nbase + ni*8;
            float* r0 = g_attn + ((size_t)n*QPOS + m0)*LTOT + nc;
            float* r1 = r0 + 8*LTOT;
            *reinterpret_cast<float2*>(r0) = make_float2(acc[mi][ni][0], acc[mi][ni][1]);
            *reinterpret_cast<float2*>(r1) = make_float2(acc[mi][ni][2], acc[mi][ni][3]);
        }
}

// ---------------- softmax over 576 keys -> bf16 hi/lo attn -------------------------
__global__ void softmax_kernel() {
    int w    = threadIdx.x >> 5;
    int lane = threadIdx.x & 31;
    int gw = blockIdx.x * 8 + w;
    int n = gw / QPOS;
    float scale = g_scale[n];
    const float* row = g_attn + (size_t)gw * LTOT;
    __nv_bfloat16* rowb = g_attnb + (size_t)gw * AK;
    float v[18];
    float m = -1e30f;
#pragma unroll
    for (int k = 0; k < 18; k++) {
        v[k] = row[lane + 32*k] * scale;
        m = fmaxf(m, v[k]);
    }
#pragma unroll
    for (int o = 16; o; o >>= 1) m = fmaxf(m, __shfl_xor_sync(0xffffffffu, m, o));
    float s = 0.f;
#pragma unroll
    for (int k = 0; k < 18; k++) { v[k] = __expf(v[k] - m); s += v[k]; }
#pragma unroll
    for (int o = 16; o; o >>= 1) s += __shfl_xor_sync(0xffffffffu, s, o);
    float inv = 1.f / s;
#pragma unroll
    for (int k = 0; k < 18; k++) {
        float val = v[k] * inv;
        __nv_bfloat16 h = __float2bfloat16(val);
        rowb[lane + 32*k] = h;
        rowb[LTOT + lane + 32*k] = __float2bfloat16(val - __bfloat162float(h));
    }
}

// ---------------- out GEMM: out2[m][200] = attn[m][:] x vb^T ------------------------
__global__ void __launch_bounds__(256, 1) out_mma() {
    extern __shared__ __align__(1024) char smem[];
    const int t = threadIdx.x, lane = t & 31, wid = t >> 5;
    const int wm = wid >> 1, wn = wid & 1;
    const int mtile = blockIdx.x, n = blockIdx.z;
    const uint32_t sb = smem_u32(smem);

    const __nv_bfloat16* Abase = g_attnb + ((size_t)n*QPOS + mtile*G2_M)*AK;
    const __nv_bfloat16* Bbase = g_vb + (size_t)n*G2_N*AK;

    float acc[2][16][4];
#pragma unroll
    for (int a = 0; a < 2; a++)
#pragma unroll
        for (int b = 0; b < 16; b++)
#pragma unroll
            for (int c = 0; c < 4; c++) acc[a][b][c] = 0.f;

    auto issue_chunk = [&](int kk, int s) {
        int ka, kb;
        if (kk < 9)       { ka = kk*64;                kb = kk*64; }
        else if (kk < 18) { ka = LTOT + (kk-9)*64;     kb = (kk-9)*64; }
        else              { ka = (kk-18)*64;           kb = LTOT + (kk-18)*64; }
        uint32_t As = sb + s*G2_STAGE;
        uint32_t Bs = As + G2_SMA;
#pragma unroll
        for (int e = 0; e < 4; e++) {
            int idx = t + e*256;
            int row = idx >> 3, col = idx & 7;
            uint32_t off = (uint32_t)row*128 + col*16;
            cp16(As + SWZB(off), Abase + (size_t)row*AK + ka + col*8);
        }
#pragma unroll
        for (int e = 0; e < 8; e++) {
            int idx = t + e*256;
            int row = idx >> 3, col = idx & 7;
            uint32_t off = (uint32_t)row*128 + col*16;
            cp16(Bs + SWZB(off), Bbase + (size_t)row*AK + kb + col*8);
        }
        asm volatile("cp.async.commit_group;");
    };

    issue_chunk(0, 0);
    asm volatile("cp.async.wait_group 0;");
    __syncthreads();

    for (int kk = 0; kk < G2_NCHUNK; kk++) {
        int s = kk & 1;
        if (kk < G2_NCHUNK-1) issue_chunk(kk + 1, s ^ 1);

        uint32_t As = sb + s*G2_STAGE;
        uint32_t Bs = As + G2_SMA;
#pragma unroll
        for (int st = 0; st < 4; st++) {
            int kbyte = st*32 + (lane >> 4)*16;
            uint32_t a[2][4];
#pragma unroll
            for (int mi = 0; mi < 2; mi++) {
                uint32_t off = (uint32_t)(wm*32 + mi*16 + (lane & 15))*128 + kbyte;
                ldsm4(a[mi], As + SWZB(off));
            }
            uint32_t b[8][4];
#pragma unroll
            for (int nj = 0; nj < 8; nj++) {
                uint32_t off = (uint32_t)(wn*128 + nj*16 + (lane & 15))*128 + kbyte;
                ldsm4(b[nj], Bs + SWZB(off));
            }
#pragma unroll
            for (int mi = 0; mi < 2; mi++)
#pragma unroll
                for (int ni = 0; ni < 16; ni++) {
                    int nj = ni >> 1;
                    if (ni & 1) mma_bf16(acc[mi][ni], a[mi], b[nj][1], b[nj][3]);
                    else        mma_bf16(acc[mi][ni], a[mi], b[nj][0], b[nj][2]);
                }
        }
        if (kk < G2_NCHUNK-1) asm volatile("cp.async.wait_group 0;");
        __syncthreads();
    }

    int mbase = mtile*G2_M + wm*32 + (lane >> 2);
    int nbase = wn*128 + (lane & 3)*2;
#pragma unroll
    for (int mi = 0; mi < 2; mi++)
#pragma unroll
        for (int ni = 0; ni < 16; ni++) {
            int m0 = mbase + mi*16;
            int nc = nbase + ni*8;
            float* r0 = g_out2 + ((size_t)n*QPOS + m0)*G2_N + nc;
            float* r1 = r0 + 8*G2_N;
            *reinterpret_cast<float2*>(r0) = make_float2(acc[mi][ni][0], acc[mi][ni][1]);
            *reinterpret_cast<float2*>(r1) = make_float2(acc[mi][ni][2], acc[mi][ni][3]);
        }
}

// ---------------- scatter: out2 -> res (conv_transpose geometry) --------------------
__global__ void scatter_out() {
    int idx = blockIdx.x * 256 + threadIdx.x;
    int n = blockIdx.y;
    if (idx >= HQP*HQP) return;
    int y = idx / HQP, x = idx % HQP;
    int oyA = y >> 2, iA = y & 3;  bool vA = oyA < QW;
    int oyB = oyA - 1;             bool vB = (iA == 0) && (oyB >= 0);
    int oxA = x >> 2, jA = x & 3;  bool hA = oxA < QW;
    int oxB = oxA - 1;             bool hB = (jA == 0) && (oxB >= 0);

    float acc[BAND];
#pragma unroll
    for (int b = 0; b < BAND; b++) acc[b] = 0.f;

    const float* base = g_out2 + (size_t)n*QPOS*G2_N;
#pragma unroll
    for (int ti = 0; ti < 2; ti++) {
        bool vi = ti ? vB : vA;
        if (!vi) continue;
        int oy = ti ? oyB : oyA;
        int ii = ti ? 4 : iA;
#pragma unroll
        for (int tj = 0; tj < 2; tj++) {
            bool vj = tj ? hB : hA;
            if (!vj) continue;
            int ox = tj ? oxB : oxA;
            int jj = tj ? 4 : jA;
            const float* row = base + (size_t)(oy*QW + ox)*G2_N + ii*5 + jj;
#pragma unroll
            for (int b = 0; b < BAND; b++) acc[b] += __ldg(&row[b*PP]);
        }
    }
#pragma unroll
    for (int b = 0; b < BAND; b++)
        g_res[(((size_t)n*BAND + b)*HQP + y)*HQP + x] = acc[b] * (1.f/6.f);
}

// ---------------- launch -----------------------------------------------------------
extern "C" void kernel_launch(void* const* d_in, const int* in_sizes, int n_in,
                              void* d_out, int out_size) {
    const float* ms   = (const float*)d_in[0];
    const float* pan  = (const float*)d_in[1];
    const float* pan2 = (const float*)d_in[2];
    const float* wq = (const float*)d_in[3];
    const float* bq = (const float*)d_in[4];
    const float* wk = (const float*)d_in[5];
    const float* bk = (const float*)d_in[6];
    const float* wv = (const float*)d_in[7];
    const float* bv = (const float*)d_in[8];
    const float* wr = (const float*)d_in[9];
    const float* br = (const float*)d_in[10];
    float* out = (float*)d_out;

    void* pv;
    cudaGetSymbolAddress(&pv, g_kfea); float* kfea = (float*)pv;
    cudaGetSymbolAddress(&pv, g_qfea); float* qfea = (float*)pv;
    cudaGetSymbolAddress(&pv, g_vfea); float* vfea = (float*)pv;
    cudaGetSymbolAddress(&pv, g_res);  float* res  = (float*)pv;

    cudaFuncSetAttribute(scores_mma, cudaFuncAttributeMaxDynamicSharedMemorySize, SC_TOTAL);
    cudaFuncSetAttribute(out_mma,    cudaFuncAttributeMaxDynamicSharedMemorySize, G2_TOTAL);

    // 1-3: q features, k features, keys bf16
    conv_1toC<MID, HQ, HQP> <<<dim3((HQP*HQP + 255)/256, NB), 256>>>(pan,  wq, bq, qfea);
    conv_1toC<MID, HS, HS>  <<<dim3((HS*HS   + 255)/256, NB), 256>>>(pan2, wk, bk, kfea);
    build_b_direct<<<NB*MID, LTOT>>>();

    // 4: the big one (profiled slot)
    scores_mma<<<dim3(LTOT/GM_N, QW, NB), 256, SC_TOTAL>>>();

    // v features + patches, norm scale
    conv_CtoC<BAND, HS><<<dim3((BAND*HS*HS + 255)/256, NB), 256>>>(ms, wv, bv, vfea);
    gather_v<<<NB*BAND*PP, LTOT>>>();
    ssq_b<<<NB*LTOT, 128>>>();
    max_kernel<<<NB, LTOT>>>();

    // softmax + output GEMM + scatter
    softmax_kernel<<<NB*QPOS/8, 256>>>();
    out_mma<<<dim3(QPOS/G2_M, 1, NB), 256, G2_TOTAL>>>();
    scatter_out<<<dim3((HQP*HQP + 255)/256, NB), 256>>>();

    // final conv
    conv_CtoC<BAND, HQP><<<dim3((BAND*HQP*HQP + 255)/256, NB), 256>>>(res, wr, br, out);
}